// round 1
// baseline (speedup 1.0000x reference)
#include <cuda_runtime.h>
#include <math_constants.h>

#define B_  2
#define S_  2048
#define D_  1024
#define H_  16
#define HD_ 64

// Scratch: Q,K,V in [B,H,S,HD] layout (head-major for contiguous attention tiles)
__device__ float g_Q[B_ * H_ * S_ * HD_];
__device__ float g_K[B_ * H_ * S_ * HD_];
__device__ float g_V[B_ * H_ * S_ * HD_];

// ---------------------------------------------------------------------------
// Fused QKV projection: out[z] = X @ W[z] + b[z], z in {Q,K,V}.
// Classic 128x128x8 fp32 SGEMM, 256 threads, 8x8 microtile.
// Q is pre-scaled by 1/sqrt(HD) = 0.125 in the epilogue.
// ---------------------------------------------------------------------------
__global__ __launch_bounds__(256) void qkv_kernel(
    const float* __restrict__ X,
    const float* __restrict__ Wq, const float* __restrict__ Wk, const float* __restrict__ Wv,
    const float* __restrict__ bq, const float* __restrict__ bk, const float* __restrict__ bv)
{
    const int z = blockIdx.z;
    const float* W    = (z == 0) ? Wq : (z == 1) ? Wk : Wv;
    const float* bias = (z == 0) ? bq : (z == 1) ? bk : bv;
    float* Out        = (z == 0) ? g_Q : (z == 1) ? g_K : g_V;
    const float scale = (z == 0) ? 0.125f : 1.0f;

    __shared__ float As[8][128];   // A tile transposed: As[k][m]
    __shared__ float Bs[8][128];   // B tile: Bs[k][n]

    const int tid = threadIdx.x;
    const int tx = tid & 15;        // 0..15 -> output col group
    const int ty = tid >> 4;        // 0..15 -> output row group
    const int rowBase = blockIdx.y * 128;
    const int colBase = blockIdx.x * 128;

    const int aRow = tid >> 1;            // 0..127
    const int aCol = (tid & 1) * 4;       // 0 or 4
    const int bRow = tid >> 5;            // 0..7
    const int bCol = (tid & 31) * 4;      // 0..124

    float acc[8][8];
    #pragma unroll
    for (int i = 0; i < 8; i++)
        #pragma unroll
        for (int j = 0; j < 8; j++) acc[i][j] = 0.0f;

    for (int k0 = 0; k0 < D_; k0 += 8) {
        float4 av = *(const float4*)&X[(size_t)(rowBase + aRow) * D_ + k0 + aCol];
        As[aCol + 0][aRow] = av.x;
        As[aCol + 1][aRow] = av.y;
        As[aCol + 2][aRow] = av.z;
        As[aCol + 3][aRow] = av.w;
        float4 bv4 = *(const float4*)&W[(size_t)(k0 + bRow) * D_ + colBase + bCol];
        *(float4*)&Bs[bRow][bCol] = bv4;
        __syncthreads();

        #pragma unroll
        for (int k = 0; k < 8; k++) {
            float4 a0 = *(const float4*)&As[k][ty * 8];
            float4 a1 = *(const float4*)&As[k][ty * 8 + 4];
            float4 b0 = *(const float4*)&Bs[k][tx * 8];
            float4 b1 = *(const float4*)&Bs[k][tx * 8 + 4];
            float ar[8] = {a0.x, a0.y, a0.z, a0.w, a1.x, a1.y, a1.z, a1.w};
            float br[8] = {b0.x, b0.y, b0.z, b0.w, b1.x, b1.y, b1.z, b1.w};
            #pragma unroll
            for (int i = 0; i < 8; i++)
                #pragma unroll
                for (int j = 0; j < 8; j++)
                    acc[i][j] += ar[i] * br[j];
        }
        __syncthreads();
    }

    // Epilogue: add bias, scale (Q only), scatter to [B,H,S,HD]
    #pragma unroll
    for (int i = 0; i < 8; i++) {
        const int m = rowBase + ty * 8 + i;
        const int b = m >> 11;          // /S_
        const int s = m & (S_ - 1);
        #pragma unroll
        for (int j = 0; j < 8; j++) {
            const int n = colBase + tx * 8 + j;
            const int h = n >> 6;       // /HD_
            const int d = n & (HD_ - 1);
            const float v = (acc[i][j] + bias[n]) * scale;
            Out[(((size_t)(b * H_ + h) * S_) + s) * HD_ + d] = v;
        }
    }
}

// ---------------------------------------------------------------------------
// Flash attention, fp32. One block = one (b,h) x 64-query tile.
// 256 threads as 16x16 grid, 4x4 microtiles. Q/K/P transposed in smem so all
// GEMM inner-loop reads are row-wise float4 (broadcast or conflict-free).
// ---------------------------------------------------------------------------
#define PAD 68
__global__ __launch_bounds__(256) void attn_kernel(
    const float* __restrict__ mask, float* __restrict__ out)
{
    extern __shared__ float sm[];
    float (*QsT)[PAD] = (float(*)[PAD])sm;                 // [d][row]  64x68
    float (*KsT)[PAD] = (float(*)[PAD])(sm + 64 * PAD);    // [d][row]
    float (*Vs )[PAD] = (float(*)[PAD])(sm + 2 * 64 * PAD);// [k][d]
    float (*PsT)[PAD] = (float(*)[PAD])(sm + 3 * 64 * PAD);// [k][row]

    const int tid = threadIdx.x;
    const int tx = tid & 15;
    const int ty = tid >> 4;
    const int qBase = blockIdx.x * 64;
    const int bh = blockIdx.y;
    const int b = bh >> 4;

    const float* Qp = g_Q + (size_t)bh * S_ * HD_;
    const float* Kp = g_K + (size_t)bh * S_ * HD_;
    const float* Vp = g_V + (size_t)bh * S_ * HD_;
    const float* mrow = mask + (size_t)b * S_;

    // Load Q tile transposed: 64 rows x 64 dims
    #pragma unroll
    for (int it = 0; it < 4; it++) {
        const int idx = it * 256 + tid;        // float4 index, 0..1023
        const int r  = idx >> 4;
        const int c4 = (idx & 15) << 2;
        float4 v = *(const float4*)&Qp[(size_t)(qBase + r) * HD_ + c4];
        QsT[c4 + 0][r] = v.x;
        QsT[c4 + 1][r] = v.y;
        QsT[c4 + 2][r] = v.z;
        QsT[c4 + 3][r] = v.w;
    }

    float m_run[4], l_run[4], o[4][4];
    #pragma unroll
    for (int i = 0; i < 4; i++) {
        m_run[i] = -CUDART_INF_F;
        l_run[i] = 0.0f;
        #pragma unroll
        for (int j = 0; j < 4; j++) o[i][j] = 0.0f;
    }

    for (int kt = 0; kt < S_ / 64; kt++) {
        const int kBase = kt * 64;
        __syncthreads();   // previous P.V done before K/V overwrite
        // Load K (transposed) and V (row-major) tiles
        #pragma unroll
        for (int it = 0; it < 4; it++) {
            const int idx = it * 256 + tid;
            const int r  = idx >> 4;
            const int c4 = (idx & 15) << 2;
            float4 kv = *(const float4*)&Kp[(size_t)(kBase + r) * HD_ + c4];
            KsT[c4 + 0][r] = kv.x;
            KsT[c4 + 1][r] = kv.y;
            KsT[c4 + 2][r] = kv.z;
            KsT[c4 + 3][r] = kv.w;
            float4 vv = *(const float4*)&Vp[(size_t)(kBase + r) * HD_ + c4];
            *(float4*)&Vs[r][c4] = vv;
        }
        __syncthreads();

        // S = Q K^T  (Q already scaled by 1/8)
        float s4[4][4];
        #pragma unroll
        for (int i = 0; i < 4; i++)
            #pragma unroll
            for (int j = 0; j < 4; j++) s4[i][j] = 0.0f;

        #pragma unroll 8
        for (int d = 0; d < 64; d++) {
            float4 aq = *(const float4*)&QsT[d][ty * 4];
            float4 bk = *(const float4*)&KsT[d][tx * 4];
            float ar[4] = {aq.x, aq.y, aq.z, aq.w};
            float br[4] = {bk.x, bk.y, bk.z, bk.w};
            #pragma unroll
            for (int i = 0; i < 4; i++)
                #pragma unroll
                for (int j = 0; j < 4; j++)
                    s4[i][j] += ar[i] * br[j];
        }

        // additive mask
        #pragma unroll
        for (int j = 0; j < 4; j++) {
            const float mj = mrow[kBase + tx * 4 + j];
            #pragma unroll
            for (int i = 0; i < 4; i++) s4[i][j] += mj;
        }

        // row max (within thread, then across 16 lanes)
        float mt[4];
        #pragma unroll
        for (int i = 0; i < 4; i++) {
            mt[i] = fmaxf(fmaxf(s4[i][0], s4[i][1]), fmaxf(s4[i][2], s4[i][3]));
            #pragma unroll
            for (int off = 8; off >= 1; off >>= 1)
                mt[i] = fmaxf(mt[i], __shfl_xor_sync(0xffffffffu, mt[i], off, 16));
        }

        float mn[4], corr[4], lt[4];
        #pragma unroll
        for (int i = 0; i < 4; i++) {
            mn[i] = fmaxf(m_run[i], mt[i]);
            corr[i] = __expf(m_run[i] - mn[i]);
            lt[i] = 0.0f;
        }
        #pragma unroll
        for (int i = 0; i < 4; i++)
            #pragma unroll
            for (int j = 0; j < 4; j++) {
                const float p = __expf(s4[i][j] - mn[i]);
                s4[i][j] = p;
                lt[i] += p;
            }
        #pragma unroll
        for (int i = 0; i < 4; i++) {
            #pragma unroll
            for (int off = 8; off >= 1; off >>= 1)
                lt[i] += __shfl_xor_sync(0xffffffffu, lt[i], off, 16);
            l_run[i] = l_run[i] * corr[i] + lt[i];
            m_run[i] = mn[i];
            #pragma unroll
            for (int j = 0; j < 4; j++) o[i][j] *= corr[i];
        }

        // write P transposed: PsT[kcol][qrow]
        #pragma unroll
        for (int j = 0; j < 4; j++) {
            float4 pv = make_float4(s4[0][j], s4[1][j], s4[2][j], s4[3][j]);
            *(float4*)&PsT[tx * 4 + j][ty * 4] = pv;
        }
        __syncthreads();

        // O += P V
        #pragma unroll 8
        for (int k = 0; k < 64; k++) {
            float4 pr = *(const float4*)&PsT[k][ty * 4];
            float4 vv = *(const float4*)&Vs[k][tx * 4];
            float ar[4] = {pr.x, pr.y, pr.z, pr.w};
            float br[4] = {vv.x, vv.y, vv.z, vv.w};
            #pragma unroll
            for (int i = 0; i < 4; i++)
                #pragma unroll
                for (int j = 0; j < 4; j++)
                    o[i][j] += ar[i] * br[j];
        }
    }

    // Finalize: divide by l, write [B,S,D] with D index = h*64 + (tx*4+j)
    const int h = bh & 15;
    #pragma unroll
    for (int i = 0; i < 4; i++) {
        const int q = qBase + ty * 4 + i;
        const float inv = 1.0f / l_run[i];
        float4 ov = make_float4(o[i][0] * inv, o[i][1] * inv, o[i][2] * inv, o[i][3] * inv);
        *(float4*)&out[((size_t)(b * S_ + q)) * D_ + h * HD_ + tx * 4] = ov;
    }
}

// ---------------------------------------------------------------------------
extern "C" void kernel_launch(void* const* d_in, const int* in_sizes, int n_in,
                              void* d_out, int out_size)
{
    const float* X    = (const float*)d_in[0];   // hidden_states [B,S,D]
    const float* mask = (const float*)d_in[1];   // attention_mask [B,1,1,S]
    const float* Wq   = (const float*)d_in[2];
    const float* bq   = (const float*)d_in[3];
    const float* Wk   = (const float*)d_in[4];
    const float* bk   = (const float*)d_in[5];
    const float* Wv   = (const float*)d_in[6];
    const float* bv   = (const float*)d_in[7];
    float* out = (float*)d_out;

    // QKV projections: grid (N/128, M/128, 3)
    {
        dim3 grid(D_ / 128, (B_ * S_) / 128, 3);
        qkv_kernel<<<grid, 256>>>(X, Wq, Wk, Wv, bq, bk, bv);
    }

    // Attention: grid (S/64 q-tiles, B*H)
    {
        const int smem = 4 * 64 * PAD * (int)sizeof(float);  // 69632 B
        static bool attr_set = false;
        cudaFuncSetAttribute(attn_kernel,
                             cudaFuncAttributeMaxDynamicSharedMemorySize, smem);
        (void)attr_set;
        dim3 grid(S_ / 64, B_ * H_);
        attn_kernel<<<grid, 256, smem>>>(mask, out);
    }
}

// round 2
// speedup vs baseline: 1.6587x; 1.6587x over previous
#include <cuda_runtime.h>
#include <math_constants.h>

#define B_  2
#define S_  2048
#define D_  1024
#define H_  16
#define HD_ 64

// Scratch: Q,K,V in [B,H,S,HD] layout
__device__ float g_Q[B_ * H_ * S_ * HD_];
__device__ float g_K[B_ * H_ * S_ * HD_];
__device__ float g_V[B_ * H_ * S_ * HD_];

// ---------------------------------------------------------------------------
// TF32 helpers
// ---------------------------------------------------------------------------
__device__ __forceinline__ unsigned f2tf(float x) {
    unsigned r;
    asm("cvt.rna.tf32.f32 %0, %1;" : "=r"(r) : "f"(x));
    return r;
}
__device__ __forceinline__ float tf2f(unsigned u) { return __uint_as_float(u); }

__device__ __forceinline__ void mma8(float c[4], const unsigned a[4], const unsigned b[2]) {
    asm volatile(
        "mma.sync.aligned.m16n8k8.row.col.f32.tf32.tf32.f32 "
        "{%0,%1,%2,%3},{%4,%5,%6,%7},{%8,%9},{%0,%1,%2,%3};"
        : "+f"(c[0]), "+f"(c[1]), "+f"(c[2]), "+f"(c[3])
        : "r"(a[0]), "r"(a[1]), "r"(a[2]), "r"(a[3]), "r"(b[0]), "r"(b[1]));
}

// ---------------------------------------------------------------------------
// QKV projection: out[z] = X @ W[z] + b[z], 3xTF32 mma. 128x128x16 tiles.
// 256 threads = 8 warps (4m x 2n), warp tile 32x64.
// ---------------------------------------------------------------------------
#define QLDA 136
__global__ __launch_bounds__(256) void qkv_kernel(
    const float* __restrict__ X,
    const float* __restrict__ Wq, const float* __restrict__ Wk, const float* __restrict__ Wv,
    const float* __restrict__ bq, const float* __restrict__ bk, const float* __restrict__ bv)
{
    const int z = blockIdx.z;
    const float* W    = (z == 0) ? Wq : (z == 1) ? Wk : Wv;
    const float* bias = (z == 0) ? bq : (z == 1) ? bk : bv;
    float* Out        = (z == 0) ? g_Q : (z == 1) ? g_K : g_V;
    const float scale = (z == 0) ? 0.125f : 1.0f;

    // A stored K-major: Ah[k][m]; B stored row-major: Bh[k][n]. hi/lo pairs.
    __shared__ float Ah[16][QLDA], Al[16][QLDA];
    __shared__ float Bh[16][QLDA], Bl[16][QLDA];

    const int tid  = threadIdx.x;
    const int lane = tid & 31;
    const int warp = tid >> 5;
    const int wm = warp & 3;        // 0..3 -> m offset wm*32
    const int wn = warp >> 2;       // 0..1 -> n offset wn*64
    const int rowBase = blockIdx.y * 128;
    const int colBase = blockIdx.x * 128;
    const int g  = lane >> 2;       // group id 0..7
    const int t  = lane & 3;        // thread-in-group 0..3

    float acc[2][8][4];
    #pragma unroll
    for (int mt = 0; mt < 2; mt++)
        #pragma unroll
        for (int nt = 0; nt < 8; nt++)
            #pragma unroll
            for (int i = 0; i < 4; i++) acc[mt][nt][i] = 0.0f;

    for (int k0 = 0; k0 < D_; k0 += 16) {
        __syncthreads();
        // A tile 128x16 -> transposed hi/lo
        #pragma unroll
        for (int i = 0; i < 2; i++) {
            const int idx = i * 256 + tid;
            const int r  = idx >> 2;
            const int c4 = (idx & 3) * 4;
            float4 v = *(const float4*)&X[(size_t)(rowBase + r) * D_ + k0 + c4];
            float vv[4] = {v.x, v.y, v.z, v.w};
            #pragma unroll
            for (int c = 0; c < 4; c++) {
                unsigned h = f2tf(vv[c]);
                Ah[c4 + c][r] = tf2f(h);
                Al[c4 + c][r] = tf2f(f2tf(vv[c] - tf2f(h)));
            }
        }
        // B tile 16x128 hi/lo
        #pragma unroll
        for (int i = 0; i < 2; i++) {
            const int idx = i * 256 + tid;
            const int r  = idx >> 5;
            const int c4 = (idx & 31) * 4;
            float4 v = *(const float4*)&W[(size_t)(k0 + r) * D_ + colBase + c4];
            float vv[4] = {v.x, v.y, v.z, v.w};
            #pragma unroll
            for (int c = 0; c < 4; c++) {
                unsigned h = f2tf(vv[c]);
                Bh[r][c4 + c] = tf2f(h);
                Bl[r][c4 + c] = tf2f(f2tf(vv[c] - tf2f(h)));
            }
        }
        __syncthreads();

        #pragma unroll
        for (int kk = 0; kk < 2; kk++) {
            const int kb = kk * 8;
            unsigned a_h[2][4], a_l[2][4];
            #pragma unroll
            for (int mt = 0; mt < 2; mt++) {
                const int mr = wm * 32 + mt * 16 + g;
                a_h[mt][0] = __float_as_uint(Ah[kb + t    ][mr    ]);
                a_h[mt][1] = __float_as_uint(Ah[kb + t    ][mr + 8]);
                a_h[mt][2] = __float_as_uint(Ah[kb + t + 4][mr    ]);
                a_h[mt][3] = __float_as_uint(Ah[kb + t + 4][mr + 8]);
                a_l[mt][0] = __float_as_uint(Al[kb + t    ][mr    ]);
                a_l[mt][1] = __float_as_uint(Al[kb + t    ][mr + 8]);
                a_l[mt][2] = __float_as_uint(Al[kb + t + 4][mr    ]);
                a_l[mt][3] = __float_as_uint(Al[kb + t + 4][mr + 8]);
            }
            #pragma unroll
            for (int nt = 0; nt < 8; nt++) {
                const int nc = wn * 64 + nt * 8 + g;
                unsigned b_h[2], b_l[2];
                b_h[0] = __float_as_uint(Bh[kb + t    ][nc]);
                b_h[1] = __float_as_uint(Bh[kb + t + 4][nc]);
                b_l[0] = __float_as_uint(Bl[kb + t    ][nc]);
                b_l[1] = __float_as_uint(Bl[kb + t + 4][nc]);
                #pragma unroll
                for (int mt = 0; mt < 2; mt++) {
                    mma8(acc[mt][nt], a_h[mt], b_h);
                    mma8(acc[mt][nt], a_h[mt], b_l);
                    mma8(acc[mt][nt], a_l[mt], b_h);
                }
            }
        }
    }

    // Epilogue: bias, scale, scatter to [B,H,S,HD]
    #pragma unroll
    for (int mt = 0; mt < 2; mt++) {
        #pragma unroll
        for (int nt = 0; nt < 8; nt++) {
            const int n0 = colBase + wn * 64 + nt * 8 + 2 * t;
            #pragma unroll
            for (int i = 0; i < 4; i++) {
                const int m = rowBase + wm * 32 + mt * 16 + g + ((i >> 1) ? 8 : 0);
                const int n = n0 + (i & 1);
                const int b = m >> 11;
                const int s = m & (S_ - 1);
                const int h = n >> 6;
                const int d = n & (HD_ - 1);
                Out[(((size_t)(b * H_ + h) * S_) + s) * HD_ + d] =
                    (acc[mt][nt][i] + bias[n]) * scale;
            }
        }
    }
}

// ---------------------------------------------------------------------------
// Flash attention, TF32 mma. Block = 64 queries x one (b,h). 128 threads,
// 4 warps; each warp owns 16 q-rows across ALL 64 key-cols per tile.
// QK^T 3xTF32, PV single TF32. Q hi/lo frags register-resident.
// ---------------------------------------------------------------------------
#define ALD 72
__global__ __launch_bounds__(128) void attn_kernel(
    const float* __restrict__ mask, float* __restrict__ out)
{
    extern __shared__ float sm[];
    float* Kh = sm;                  // [64][72] tf32 hi
    float* Kl = sm + 64 * ALD;       // [64][72] tf32 lo
    float* Vh = sm + 2 * 64 * ALD;   // [64][72] tf32
    float* Ps = sm + 3 * 64 * ALD;   // [64][72] P (tf32), also Q staging
    float* ms = sm + 4 * 64 * ALD;   // [2048] mask row

    const int tid  = threadIdx.x;
    const int lane = tid & 31;
    const int warp = tid >> 5;
    const int g = lane >> 2;
    const int t = lane & 3;
    const int qBase = blockIdx.x * 64;
    const int bh = blockIdx.y;
    const int b = bh >> 4;
    const int h = bh & 15;

    const float* Qp = g_Q + (size_t)bh * S_ * HD_;
    const float* Kp = g_K + (size_t)bh * S_ * HD_;
    const float* Vp = g_V + (size_t)bh * S_ * HD_;

    // mask row -> smem
    #pragma unroll
    for (int i = 0; i < 4; i++) {
        const int idx = i * 128 + tid;
        *(float4*)&ms[idx * 4] = *(const float4*)&mask[(size_t)b * S_ + idx * 4];
    }
    // Q tile -> smem staging (raw fp32)
    #pragma unroll
    for (int i = 0; i < 8; i++) {
        const int idx = i * 128 + tid;
        const int r  = idx >> 4;
        const int c4 = (idx & 15) * 4;
        *(float4*)&Ps[r * ALD + c4] = *(const float4*)&Qp[(size_t)(qBase + r) * HD_ + c4];
    }
    __syncthreads();

    // Build Q frags (register-resident across all K tiles)
    unsigned qh[8][4], ql[8][4];
    const int qr = warp * 16 + g;
    #pragma unroll
    for (int kk = 0; kk < 8; kk++) {
        const int c0 = kk * 8 + t;
        float f0 = Ps[ qr      * ALD + c0    ];
        float f1 = Ps[(qr + 8) * ALD + c0    ];
        float f2 = Ps[ qr      * ALD + c0 + 4];
        float f3 = Ps[(qr + 8) * ALD + c0 + 4];
        qh[kk][0] = f2tf(f0); ql[kk][0] = f2tf(f0 - tf2f(qh[kk][0]));
        qh[kk][1] = f2tf(f1); ql[kk][1] = f2tf(f1 - tf2f(qh[kk][1]));
        qh[kk][2] = f2tf(f2); ql[kk][2] = f2tf(f2 - tf2f(qh[kk][2]));
        qh[kk][3] = f2tf(f3); ql[kk][3] = f2tf(f3 - tf2f(qh[kk][3]));
    }

    float m_run0 = -CUDART_INF_F, m_run1 = -CUDART_INF_F;
    float l_run0 = 0.0f, l_run1 = 0.0f;
    float o[8][4];
    #pragma unroll
    for (int nt = 0; nt < 8; nt++)
        #pragma unroll
        for (int i = 0; i < 4; i++) o[nt][i] = 0.0f;

    for (int kt = 0; kt < S_ / 64; kt++) {
        const int kBase = kt * 64;
        __syncthreads();   // previous tile fully consumed (also guards Q staging)

        // Load K (hi/lo) and V (tf32) tiles
        #pragma unroll
        for (int i = 0; i < 8; i++) {
            const int idx = i * 128 + tid;
            const int r  = idx >> 4;
            const int c4 = (idx & 15) * 4;
            float4 kv = *(const float4*)&Kp[(size_t)(kBase + r) * HD_ + c4];
            float4 vv = *(const float4*)&Vp[(size_t)(kBase + r) * HD_ + c4];
            float kk4[4] = {kv.x, kv.y, kv.z, kv.w};
            float vv4[4] = {vv.x, vv.y, vv.z, vv.w};
            #pragma unroll
            for (int c = 0; c < 4; c++) {
                unsigned hh = f2tf(kk4[c]);
                Kh[r * ALD + c4 + c] = tf2f(hh);
                Kl[r * ALD + c4 + c] = tf2f(f2tf(kk4[c] - tf2f(hh)));
                Vh[r * ALD + c4 + c] = tf2f(f2tf(vv4[c]));
            }
        }
        __syncthreads();

        // S = Q K^T (3xTF32)
        float s[8][4];
        #pragma unroll
        for (int nt = 0; nt < 8; nt++)
            #pragma unroll
            for (int i = 0; i < 4; i++) s[nt][i] = 0.0f;

        #pragma unroll
        for (int kk = 0; kk < 8; kk++) {
            #pragma unroll
            for (int nt = 0; nt < 8; nt++) {
                const int kcol = nt * 8 + g;       // key within tile
                const int d0   = kk * 8 + t;       // head-dim
                unsigned b_h[2], b_l[2];
                b_h[0] = __float_as_uint(Kh[kcol * ALD + d0    ]);
                b_h[1] = __float_as_uint(Kh[kcol * ALD + d0 + 4]);
                b_l[0] = __float_as_uint(Kl[kcol * ALD + d0    ]);
                b_l[1] = __float_as_uint(Kl[kcol * ALD + d0 + 4]);
                mma8(s[nt], qh[kk], b_h);
                mma8(s[nt], qh[kk], b_l);
                mma8(s[nt], ql[kk], b_h);
            }
        }

        // mask add
        #pragma unroll
        for (int nt = 0; nt < 8; nt++) {
            const int c = kBase + nt * 8 + 2 * t;
            const float mk0 = ms[c], mk1 = ms[c + 1];
            s[nt][0] += mk0; s[nt][1] += mk1;
            s[nt][2] += mk0; s[nt][3] += mk1;
        }

        // Online softmax (rows qr and qr+8; reductions within quad)
        float mx0 = -CUDART_INF_F, mx1 = -CUDART_INF_F;
        #pragma unroll
        for (int nt = 0; nt < 8; nt++) {
            mx0 = fmaxf(mx0, fmaxf(s[nt][0], s[nt][1]));
            mx1 = fmaxf(mx1, fmaxf(s[nt][2], s[nt][3]));
        }
        mx0 = fmaxf(mx0, __shfl_xor_sync(0xffffffffu, mx0, 1));
        mx0 = fmaxf(mx0, __shfl_xor_sync(0xffffffffu, mx0, 2));
        mx1 = fmaxf(mx1, __shfl_xor_sync(0xffffffffu, mx1, 1));
        mx1 = fmaxf(mx1, __shfl_xor_sync(0xffffffffu, mx1, 2));

        const float mn0 = fmaxf(m_run0, mx0);
        const float mn1 = fmaxf(m_run1, mx1);
        const float corr0 = __expf(m_run0 - mn0);
        const float corr1 = __expf(m_run1 - mn1);

        float sum0 = 0.0f, sum1 = 0.0f;
        #pragma unroll
        for (int nt = 0; nt < 8; nt++) {
            s[nt][0] = __expf(s[nt][0] - mn0); sum0 += s[nt][0];
            s[nt][1] = __expf(s[nt][1] - mn0); sum0 += s[nt][1];
            s[nt][2] = __expf(s[nt][2] - mn1); sum1 += s[nt][2];
            s[nt][3] = __expf(s[nt][3] - mn1); sum1 += s[nt][3];
        }
        sum0 += __shfl_xor_sync(0xffffffffu, sum0, 1);
        sum0 += __shfl_xor_sync(0xffffffffu, sum0, 2);
        sum1 += __shfl_xor_sync(0xffffffffu, sum1, 1);
        sum1 += __shfl_xor_sync(0xffffffffu, sum1, 2);

        l_run0 = l_run0 * corr0 + sum0;
        l_run1 = l_run1 * corr1 + sum1;
        m_run0 = mn0; m_run1 = mn1;

        #pragma unroll
        for (int nt = 0; nt < 8; nt++) {
            o[nt][0] *= corr0; o[nt][1] *= corr0;
            o[nt][2] *= corr1; o[nt][3] *= corr1;
        }

        // P -> smem (tf32), own-warp rows only
        #pragma unroll
        for (int nt = 0; nt < 8; nt++) {
            const int c = nt * 8 + 2 * t;
            float2 p0 = make_float2(tf2f(f2tf(s[nt][0])), tf2f(f2tf(s[nt][1])));
            float2 p1 = make_float2(tf2f(f2tf(s[nt][2])), tf2f(f2tf(s[nt][3])));
            *(float2*)&Ps[ qr      * ALD + c] = p0;
            *(float2*)&Ps[(qr + 8) * ALD + c] = p1;
        }
        __syncwarp();

        // O += P V (single TF32)
        #pragma unroll
        for (int kk = 0; kk < 8; kk++) {
            const int pk = kk * 8 + t;
            unsigned pa[4];
            pa[0] = __float_as_uint(Ps[ qr      * ALD + pk    ]);
            pa[1] = __float_as_uint(Ps[(qr + 8) * ALD + pk    ]);
            pa[2] = __float_as_uint(Ps[ qr      * ALD + pk + 4]);
            pa[3] = __float_as_uint(Ps[(qr + 8) * ALD + pk + 4]);
            #pragma unroll
            for (int nt = 0; nt < 8; nt++) {
                const int dcol = nt * 8 + g;
                unsigned vb[2];
                vb[0] = __float_as_uint(Vh[(kk * 8 + t    ) * ALD + dcol]);
                vb[1] = __float_as_uint(Vh[(kk * 8 + t + 4) * ALD + dcol]);
                mma8(o[nt], pa, vb);
            }
        }
    }

    // Finalize
    const float inv0 = 1.0f / l_run0;
    const float inv1 = 1.0f / l_run1;
    const int q0 = qBase + qr;
    #pragma unroll
    for (int nt = 0; nt < 8; nt++) {
        const int d = h * 64 + nt * 8 + 2 * t;
        float2 v0 = make_float2(o[nt][0] * inv0, o[nt][1] * inv0);
        float2 v1 = make_float2(o[nt][2] * inv1, o[nt][3] * inv1);
        *(float2*)&out[((size_t)(b * S_ + q0    )) * D_ + d] = v0;
        *(float2*)&out[((size_t)(b * S_ + q0 + 8)) * D_ + d] = v1;
    }
}

// ---------------------------------------------------------------------------
extern "C" void kernel_launch(void* const* d_in, const int* in_sizes, int n_in,
                              void* d_out, int out_size)
{
    const float* X    = (const float*)d_in[0];
    const float* mask = (const float*)d_in[1];
    const float* Wq   = (const float*)d_in[2];
    const float* bq   = (const float*)d_in[3];
    const float* Wk   = (const float*)d_in[4];
    const float* bk   = (const float*)d_in[5];
    const float* Wv   = (const float*)d_in[6];
    const float* bv   = (const float*)d_in[7];
    float* out = (float*)d_out;

    {
        dim3 grid(D_ / 128, (B_ * S_) / 128, 3);
        qkv_kernel<<<grid, 256>>>(X, Wq, Wk, Wv, bq, bk, bv);
    }
    {
        const int smem = (4 * 64 * ALD + 2048) * (int)sizeof(float);  // 81920 B
        cudaFuncSetAttribute(attn_kernel,
                             cudaFuncAttributeMaxDynamicSharedMemorySize, smem);
        dim3 grid(S_ / 64, B_ * H_);
        attn_kernel<<<grid, 128, smem>>>(mask, out);
    }
}